// round 1
// baseline (speedup 1.0000x reference)
#include <cuda_runtime.h>
#include <math.h>
#include <stdint.h>

#define Nn 20000
#define F_INn 256
#define HIDn 256
#define EMBn 128
#define HEADSn 8
#define NE 160000
#define NEG_SLOPE 0.2f

// ---------------- scratch (device globals; no cudaMalloc allowed) ----------
__device__ float g_bufA[(size_t)Nn * 1024];
__device__ float g_bufB[(size_t)Nn * 1024];
__device__ float g_dinv[Nn];
__device__ int   g_cnt[Nn];
__device__ int   g_cursor[Nn];
__device__ int   g_rowptr[Nn + 1];
__device__ int   g_col[NE];
__device__ float g_as[Nn * HEADSn];
__device__ float g_ad[Nn * HEADSn];
__device__ float g_m[Nn * HEADSn];
__device__ float g_s[Nn * HEADSn];
__device__ float g_w[Nn];
__device__ float g_partial[128];
__device__ float g_total;
__device__ int   g_is64;

// ---------------- helpers ---------------------------------------------------
__device__ __forceinline__ float lrelu(float x) { return x > 0.f ? x : NEG_SLOPE * x; }

__device__ __forceinline__ int load_idx(const void* ei, long long i) {
    if (g_is64) return (int)((const long long*)ei)[i];
    return ((const int*)ei)[i];
}

// Detect whether edge_index is int64 or int32: node ids < 20000, so if int64
// every odd 32-bit word (high half) is zero. Probability of 64 random int32
// src ids all being zero is ~0.
__global__ void k_detect(const int* __restrict__ ei32) {
    if (threadIdx.x == 0) {
        int is64 = 1;
        for (int i = 1; i < 128; i += 2)
            if (ei32[i] != 0) { is64 = 0; break; }
        g_is64 = is64;
    }
}

// ---------------- CSR build -------------------------------------------------
__global__ void k_zero_counts() {
    int i = blockIdx.x * blockDim.x + threadIdx.x;
    if (i < Nn) { g_cnt[i] = 0; g_cursor[i] = 0; }
}

__global__ void k_count(const void* __restrict__ ei) {
    int e = blockIdx.x * blockDim.x + threadIdx.x;
    if (e < NE) atomicAdd(&g_cnt[load_idx(ei, (long long)NE + e)], 1);
}

__global__ void k_dinv() {
    int i = blockIdx.x * blockDim.x + threadIdx.x;
    if (i < Nn) g_dinv[i] = rsqrtf((float)(g_cnt[i] + 1)); // +1 self-loop
}

__global__ void k_scan() {
    __shared__ int tmp[1024];
    __shared__ int s_base;
    int tid = threadIdx.x;
    if (tid == 0) { s_base = 0; g_rowptr[0] = 0; }
    __syncthreads();
    for (int start = 0; start < Nn; start += 1024) {
        int i = start + tid;
        int v = (i < Nn) ? g_cnt[i] : 0;
        tmp[tid] = v;
        __syncthreads();
        for (int d = 1; d < 1024; d <<= 1) {
            int t = (tid >= d) ? tmp[tid - d] : 0;
            __syncthreads();
            tmp[tid] += t;
            __syncthreads();
        }
        int b = s_base;
        if (i < Nn) g_rowptr[i + 1] = b + tmp[tid];
        __syncthreads();
        if (tid == 1023) s_base = b + tmp[1023];
        __syncthreads();
    }
}

__global__ void k_fill(const void* __restrict__ ei) {
    int e = blockIdx.x * blockDim.x + threadIdx.x;
    if (e < NE) {
        int s = load_idx(ei, e);
        int d = load_idx(ei, (long long)NE + e);
        int p = g_rowptr[d] + atomicAdd(&g_cursor[d], 1);
        g_col[p] = s;
    }
}

// ---------------- SGEMM: C[M,N] = A[M,K] @ B[K,N] (+bias)(+relu) -----------
// BM=128, BN=64, BK=16, 256 threads, 8x4 per thread.
__global__ void __launch_bounds__(256) k_sgemm(
    const float* __restrict__ A, const float* __restrict__ B,
    const float* __restrict__ bias, float* __restrict__ C,
    int M, int N, int K, int relu)
{
    __shared__ __align__(16) float As[16][132];
    __shared__ __align__(16) float Bs[16][64];
    int tx = threadIdx.x & 15;   // N direction
    int ty = threadIdx.x >> 4;   // M direction
    int m0 = blockIdx.y * 128;
    int n0 = blockIdx.x * 64;
    float acc[8][4];
#pragma unroll
    for (int i = 0; i < 8; i++)
#pragma unroll
        for (int j = 0; j < 4; j++) acc[i][j] = 0.f;

    for (int kk = 0; kk < K; kk += 16) {
#pragma unroll
        for (int r = 0; r < 2; r++) {
            int f = threadIdx.x + r * 256;     // 0..511
            int row = f >> 2;                   // 0..127
            int kq = (f & 3) << 2;              // 0,4,8,12
            float4 v = make_float4(0.f, 0.f, 0.f, 0.f);
            int gm = m0 + row;
            if (gm < M)
                v = *reinterpret_cast<const float4*>(A + (size_t)gm * K + kk + kq);
            As[kq + 0][row] = v.x; As[kq + 1][row] = v.y;
            As[kq + 2][row] = v.z; As[kq + 3][row] = v.w;
        }
        {
            int krow = threadIdx.x >> 4;        // 0..15
            int nq = (threadIdx.x & 15) << 2;   // 0..60
            float4 v = *reinterpret_cast<const float4*>(
                B + (size_t)(kk + krow) * N + n0 + nq);
            *reinterpret_cast<float4*>(&Bs[krow][nq]) = v;
        }
        __syncthreads();
#pragma unroll
        for (int k = 0; k < 16; k++) {
            float4 b4 = *reinterpret_cast<const float4*>(&Bs[k][tx << 2]);
            float4 a0 = *reinterpret_cast<const float4*>(&As[k][ty << 3]);
            float4 a1 = *reinterpret_cast<const float4*>(&As[k][(ty << 3) + 4]);
            float am[8] = {a0.x, a0.y, a0.z, a0.w, a1.x, a1.y, a1.z, a1.w};
            float bv[4] = {b4.x, b4.y, b4.z, b4.w};
#pragma unroll
            for (int i = 0; i < 8; i++)
#pragma unroll
                for (int j = 0; j < 4; j++)
                    acc[i][j] = fmaf(am[i], bv[j], acc[i][j]);
        }
        __syncthreads();
    }
#pragma unroll
    for (int i = 0; i < 8; i++) {
        int gm = m0 + (ty << 3) + i;
        if (gm >= M) continue;
#pragma unroll
        for (int j = 0; j < 4; j++) {
            int gn = n0 + (tx << 2) + j;
            float v = acc[i][j];
            if (bias) v += bias[gn];
            if (relu) v = fmaxf(v, 0.f);
            C[(size_t)gm * N + gn] = v;
        }
    }
}

// ---------------- GCN aggregation: warp per node ----------------------------
// out[i,:] = relu( dinv[i] * ( dinv[i]*t[i,:] + sum_e dinv[src]*t[src,:] ) + bias )
template <int F>
__global__ void k_gcn_agg(const float* __restrict__ t,
                          const float* __restrict__ bias,
                          float* __restrict__ out)
{
    int node = blockIdx.x * (blockDim.x >> 5) + (threadIdx.x >> 5);
    if (node >= Nn) return;
    int lane = threadIdx.x & 31;
    float acc[F / 32];
    float di = g_dinv[node];
    const float* selfrow = t + (size_t)node * F;
#pragma unroll
    for (int j = 0; j < F / 32; j++) acc[j] = di * selfrow[lane + 32 * j];
    int beg = g_rowptr[node], end = g_rowptr[node + 1];
    for (int p = beg; p < end; ++p) {
        int s = g_col[p];
        float c = g_dinv[s];
        const float* row = t + (size_t)s * F;
#pragma unroll
        for (int j = 0; j < F / 32; j++)
            acc[j] = fmaf(c, row[lane + 32 * j], acc[j]);
    }
#pragma unroll
    for (int j = 0; j < F / 32; j++) {
        float v = di * acc[j] + bias[lane + 32 * j];
        out[(size_t)node * F + lane + 32 * j] = fmaxf(v, 0.f);
    }
}

// ---------------- GAT: per-node attention scores ----------------------------
__global__ void k_gat_scores(const float* __restrict__ hg,
                             const float* __restrict__ att_src,
                             const float* __restrict__ att_dst)
{
    int node = blockIdx.x * (blockDim.x >> 5) + (threadIdx.x >> 5);
    if (node >= Nn) return;
    int lane = threadIdx.x & 31;
    const float* base = hg + (size_t)node * (HEADSn * EMBn);
#pragma unroll
    for (int h = 0; h < HEADSn; ++h) {
        float vs = 0.f, vd = 0.f;
#pragma unroll
        for (int j = 0; j < 4; j++) {
            float xv = base[h * EMBn + lane + 32 * j];
            vs = fmaf(xv, att_src[h * EMBn + lane + 32 * j], vs);
            vd = fmaf(xv, att_dst[h * EMBn + lane + 32 * j], vd);
        }
#pragma unroll
        for (int o = 16; o > 0; o >>= 1) {
            vs += __shfl_down_sync(0xffffffffu, vs, o);
            vd += __shfl_down_sync(0xffffffffu, vd, o);
        }
        if (lane == 0) {
            g_as[node * HEADSn + h] = vs;
            g_ad[node * HEADSn + h] = vd;
        }
    }
}

// ---------------- GAT: online max/sum per (node, head) ----------------------
__global__ void k_gat_stats() {
    int t = blockIdx.x * blockDim.x + threadIdx.x;
    if (t >= Nn * HEADSn) return;
    int node = t >> 3;
    int h = t & 7;
    float ad = g_ad[t];
    float m = lrelu(g_as[t] + ad);   // self loop
    float s = 1.0f;
    int beg = g_rowptr[node], end = g_rowptr[node + 1];
    for (int p = beg; p < end; ++p) {
        int src = g_col[p];
        float e = lrelu(g_as[src * HEADSn + h] + ad);
        if (e > m) { s = s * __expf(m - e) + 1.f; m = e; }
        else       { s += __expf(e - m); }
    }
    g_m[t] = m; g_s[t] = s;
}

// ---------------- GAT: weighted aggregation, warp per (node, head) ----------
__global__ void k_gat_agg(const float* __restrict__ hg,
                          const float* __restrict__ bg,
                          float* __restrict__ out)
{
    int node = blockIdx.x;
    int h = threadIdx.x >> 5;
    int lane = threadIdx.x & 31;
    int t = node * HEADSn + h;
    float m = g_m[t];
    float sinv = 1.0f / g_s[t];
    float ad = g_ad[t];
    float acc[4];
    float aself = __expf(lrelu(g_as[t] + ad) - m) * sinv;
    const float* srow = hg + (size_t)node * (HEADSn * EMBn) + h * EMBn;
#pragma unroll
    for (int j = 0; j < 4; j++) acc[j] = aself * srow[lane + 32 * j];
    int beg = g_rowptr[node], end = g_rowptr[node + 1];
    for (int p = beg; p < end; ++p) {
        int src = g_col[p];
        float alpha = __expf(lrelu(g_as[src * HEADSn + h] + ad) - m) * sinv;
        const float* row = hg + (size_t)src * (HEADSn * EMBn) + h * EMBn;
#pragma unroll
        for (int j = 0; j < 4; j++)
            acc[j] = fmaf(alpha, row[lane + 32 * j], acc[j]);
    }
#pragma unroll
    for (int j = 0; j < 4; j++)
        out[(size_t)node * (HEADSn * EMBn) + h * EMBn + lane + 32 * j] =
            acc[j] + bg[h * EMBn + lane + 32 * j];
}

// ---------------- head: logits -> sigmoid ------------------------------------
__global__ void k_logits(const float* __restrict__ z,
                         const float* __restrict__ Wh2,
                         const float* __restrict__ bh2)
{
    int node = blockIdx.x * (blockDim.x >> 5) + (threadIdx.x >> 5);
    if (node >= Nn) return;
    int lane = threadIdx.x & 31;
    float v = 0.f;
    const float* row = z + (size_t)node * HIDn;
#pragma unroll
    for (int j = 0; j < HIDn / 32; j++)
        v = fmaf(row[lane + 32 * j], Wh2[lane + 32 * j], v);
#pragma unroll
    for (int o = 16; o > 0; o >>= 1) v += __shfl_down_sync(0xffffffffu, v, o);
    if (lane == 0) {
        float logit = v + bh2[0];
        g_w[node] = 1.0f / (1.0f + __expf(-logit));
    }
}

// ---------------- softmax over all N (deterministic two-level) --------------
__global__ void k_exp_partial() {
    __shared__ float red[256];
    int i = blockIdx.x * 256 + threadIdx.x;
    float e = 0.f;
    if (i < Nn) { e = __expf(g_w[i]); g_w[i] = e; }
    red[threadIdx.x] = e;
    __syncthreads();
    for (int o = 128; o > 0; o >>= 1) {
        if (threadIdx.x < o) red[threadIdx.x] += red[threadIdx.x + o];
        __syncthreads();
    }
    if (threadIdx.x == 0) g_partial[blockIdx.x] = red[0];
}

__global__ void k_sum_partials(int nb) {
    __shared__ float red[128];
    float v = ((int)threadIdx.x < nb) ? g_partial[threadIdx.x] : 0.f;
    red[threadIdx.x] = v;
    __syncthreads();
    for (int o = 64; o > 0; o >>= 1) {
        if (threadIdx.x < o) red[threadIdx.x] += red[threadIdx.x + o];
        __syncthreads();
    }
    if (threadIdx.x == 0) g_total = red[0];
}

__global__ void k_normalize(float* __restrict__ out) {
    int i = blockIdx.x * blockDim.x + threadIdx.x;
    if (i < Nn) out[i] = g_w[i] / g_total;
}

// ---------------- launch ------------------------------------------------------
extern "C" void kernel_launch(void* const* d_in, const int* in_sizes, int n_in,
                              void* d_out, int out_size)
{
    const float* x        = (const float*)d_in[0];
    const void*  ei       = d_in[1];
    const float* W1       = (const float*)d_in[2];
    const float* b1       = (const float*)d_in[3];
    const float* W2       = (const float*)d_in[4];
    const float* b2       = (const float*)d_in[5];
    const float* W3       = (const float*)d_in[6];
    const float* b3       = (const float*)d_in[7];
    const float* Wg       = (const float*)d_in[8];
    const float* att_src  = (const float*)d_in[9];
    const float* att_dst  = (const float*)d_in[10];
    const float* bg       = (const float*)d_in[11];
    const float* Wh1      = (const float*)d_in[12];
    const float* bh1      = (const float*)d_in[13];
    const float* Wh2      = (const float*)d_in[14];
    const float* bh2      = (const float*)d_in[15];
    float* out = (float*)d_out;

    float *bufA, *bufB;
    cudaGetSymbolAddress((void**)&bufA, g_bufA);
    cudaGetSymbolAddress((void**)&bufB, g_bufB);

    // Graph/CSR prep
    k_detect<<<1, 32>>>((const int*)ei);
    k_zero_counts<<<(Nn + 255) / 256, 256>>>();
    k_count<<<(NE + 255) / 256, 256>>>(ei);
    k_dinv<<<(Nn + 255) / 256, 256>>>();
    k_scan<<<1, 1024>>>();
    k_fill<<<(NE + 255) / 256, 256>>>(ei);

    dim3 blk(256);
    // GCN 1
    { dim3 g(HIDn / 64, (Nn + 127) / 128);
      k_sgemm<<<g, blk>>>(x, W1, nullptr, bufA, Nn, HIDn, F_INn, 0); }
    k_gcn_agg<HIDn><<<(Nn + 7) / 8, 256>>>(bufA, b1, bufB);
    // GCN 2
    { dim3 g(HIDn / 64, (Nn + 127) / 128);
      k_sgemm<<<g, blk>>>(bufB, W2, nullptr, bufA, Nn, HIDn, HIDn, 0); }
    k_gcn_agg<HIDn><<<(Nn + 7) / 8, 256>>>(bufA, b2, bufB);
    // GCN 3 (256 -> 128)
    { dim3 g(EMBn / 64, (Nn + 127) / 128);
      k_sgemm<<<g, blk>>>(bufB, W3, nullptr, bufA, Nn, EMBn, HIDn, 0); }
    k_gcn_agg<EMBn><<<(Nn + 7) / 8, 256>>>(bufA, b3, bufB);
    // GAT projection (128 -> 1024), no bias here (bg added post-aggregation)
    { dim3 g((HEADSn * EMBn) / 64, (Nn + 127) / 128);
      k_sgemm<<<g, blk>>>(bufB, Wg, nullptr, bufA, Nn, HEADSn * EMBn, EMBn, 0); }
    k_gat_scores<<<(Nn + 7) / 8, 256>>>(bufA, att_src, att_dst);
    k_gat_stats<<<(Nn * HEADSn + 255) / 256, 256>>>();
    k_gat_agg<<<Nn, 256>>>(bufA, bg, bufB);
    // Head MLP
    { dim3 g(HIDn / 64, (Nn + 127) / 128);
      k_sgemm<<<g, blk>>>(bufB, Wh1, bh1, bufA, Nn, HIDn, HEADSn * EMBn, 1); }
    k_logits<<<(Nn + 7) / 8, 256>>>(bufA, Wh2, bh2);
    int nb = (Nn + 255) / 256;
    k_exp_partial<<<nb, 256>>>();
    k_sum_partials<<<1, 128>>>(nb);
    k_normalize<<<nb, 256>>>(out);
}

// round 2
// speedup vs baseline: 1.7287x; 1.7287x over previous
#include <cuda_runtime.h>
#include <cuda_bf16.h>
#include <math.h>
#include <stdint.h>

#define Nn 20000
#define F_INn 256
#define HIDn 256
#define EMBn 128
#define HEADSn 8
#define NE 160000
#define NEG_SLOPE 0.2f

// ---------------- scratch (device globals; no cudaMalloc allowed) ----------
__device__ float g_bufA[(size_t)Nn * 1024];
__device__ float g_bufB[(size_t)Nn * 1024];
__device__ float g_dinv[Nn];
__device__ int   g_cnt[Nn];
__device__ int   g_cursor[Nn];
__device__ int   g_rowptr[Nn + 1];
__device__ int   g_col[NE];
__device__ float g_as[Nn * HEADSn];
__device__ float g_ad[Nn * HEADSn];
__device__ float g_m[Nn * HEADSn];
__device__ float g_s[Nn * HEADSn];
__device__ float g_w[Nn];
__device__ float g_partial[128];
__device__ float g_total;
__device__ int   g_is64;

// Split-precision weights (hi/lo bf16). Total elems:
// W1 65536, W2 65536, W3 32768, Wg 131072, Wh1 262144 = 557056
#define WOFF_W1  0
#define WOFF_W2  65536
#define WOFF_W3  131072
#define WOFF_WG  163840
#define WOFF_WH1 294912
#define WTOTAL   557056
__device__ __nv_bfloat16 g_whi[WTOTAL];
__device__ __nv_bfloat16 g_wlo[WTOTAL];

// ---------------- helpers ---------------------------------------------------
__device__ __forceinline__ float lrelu(float x) { return x > 0.f ? x : NEG_SLOPE * x; }

__device__ __forceinline__ int load_idx(const void* ei, long long i) {
    if (g_is64) return (int)((const long long*)ei)[i];
    return ((const int*)ei)[i];
}

__global__ void k_detect(const int* __restrict__ ei32) {
    if (threadIdx.x == 0) {
        int is64 = 1;
        for (int i = 1; i < 128; i += 2)
            if (ei32[i] != 0) { is64 = 0; break; }
        g_is64 = is64;
    }
}

// ---------------- CSR build -------------------------------------------------
__global__ void k_zero_counts() {
    int i = blockIdx.x * blockDim.x + threadIdx.x;
    if (i < Nn) { g_cnt[i] = 0; g_cursor[i] = 0; }
}

__global__ void k_count(const void* __restrict__ ei) {
    int e = blockIdx.x * blockDim.x + threadIdx.x;
    if (e < NE) atomicAdd(&g_cnt[load_idx(ei, (long long)NE + e)], 1);
}

__global__ void k_dinv() {
    int i = blockIdx.x * blockDim.x + threadIdx.x;
    if (i < Nn) g_dinv[i] = rsqrtf((float)(g_cnt[i] + 1));
}

__global__ void k_scan() {
    __shared__ int tmp[1024];
    __shared__ int s_base;
    int tid = threadIdx.x;
    if (tid == 0) { s_base = 0; g_rowptr[0] = 0; }
    __syncthreads();
    for (int start = 0; start < Nn; start += 1024) {
        int i = start + tid;
        int v = (i < Nn) ? g_cnt[i] : 0;
        tmp[tid] = v;
        __syncthreads();
        for (int d = 1; d < 1024; d <<= 1) {
            int t = (tid >= d) ? tmp[tid - d] : 0;
            __syncthreads();
            tmp[tid] += t;
            __syncthreads();
        }
        int b = s_base;
        if (i < Nn) g_rowptr[i + 1] = b + tmp[tid];
        __syncthreads();
        if (tid == 1023) s_base = b + tmp[1023];
        __syncthreads();
    }
}

__global__ void k_fill(const void* __restrict__ ei) {
    int e = blockIdx.x * blockDim.x + threadIdx.x;
    if (e < NE) {
        int s = load_idx(ei, e);
        int d = load_idx(ei, (long long)NE + e);
        int p = g_rowptr[d] + atomicAdd(&g_cursor[d], 1);
        g_col[p] = s;
    }
}

// ---------------- weight split: fp32 -> bf16 hi + bf16 lo -------------------
__global__ void k_split(const float* __restrict__ src,
                        __nv_bfloat16* __restrict__ hi,
                        __nv_bfloat16* __restrict__ lo, int n) {
    int i = blockIdx.x * blockDim.x + threadIdx.x;
    if (i < n) {
        float v = src[i];
        __nv_bfloat16 h = __float2bfloat16_rn(v);
        float r = v - __bfloat162float(h);
        hi[i] = h;
        lo[i] = __float2bfloat16_rn(r);
    }
}

// ---------------- tensor-core GEMM (bf16 split, 3 MMA products) -------------
// C[M,N] = A[M,K](fp32) @ B[K,N](pre-split bf16 hi/lo), optional bias + relu.
// BM=128 BN=64 BK=32, 256 threads = 8 warps (4m x 2n), warp tile 32x32.
#define BM 128
#define BN 64
#define BK 32
#define ASTR 40   // bf16 elems per A smem row (32 + 8 pad)
#define BSTR 72   // bf16 elems per B smem row (64 + 8 pad)

__device__ __forceinline__ uint32_t smem_u32(const void* p) {
    return (uint32_t)__cvta_generic_to_shared(p);
}
__device__ __forceinline__ void ldsm4(uint32_t* r, uint32_t a) {
    asm volatile("ldmatrix.sync.aligned.m8n8.x4.shared.b16 {%0,%1,%2,%3}, [%4];"
                 : "=r"(r[0]), "=r"(r[1]), "=r"(r[2]), "=r"(r[3]) : "r"(a));
}
__device__ __forceinline__ void ldsm4t(uint32_t* r, uint32_t a) {
    asm volatile("ldmatrix.sync.aligned.m8n8.x4.trans.shared.b16 {%0,%1,%2,%3}, [%4];"
                 : "=r"(r[0]), "=r"(r[1]), "=r"(r[2]), "=r"(r[3]) : "r"(a));
}
__device__ __forceinline__ void mma16816(float* c, const uint32_t* a, const uint32_t* b) {
    asm volatile(
        "mma.sync.aligned.m16n8k16.row.col.f32.bf16.bf16.f32 "
        "{%0,%1,%2,%3}, {%4,%5,%6,%7}, {%8,%9}, {%0,%1,%2,%3};"
        : "+f"(c[0]), "+f"(c[1]), "+f"(c[2]), "+f"(c[3])
        : "r"(a[0]), "r"(a[1]), "r"(a[2]), "r"(a[3]), "r"(b[0]), "r"(b[1]));
}

__global__ void __launch_bounds__(256) k_gemm(
    const float* __restrict__ A,
    const __nv_bfloat16* __restrict__ Bhi, const __nv_bfloat16* __restrict__ Blo,
    const float* __restrict__ bias, float* __restrict__ C,
    int M, int N, int K, int relu)
{
    __shared__ __align__(16) __nv_bfloat16 sAh[BM * ASTR];
    __shared__ __align__(16) __nv_bfloat16 sAl[BM * ASTR];
    __shared__ __align__(16) __nv_bfloat16 sBh[BK * BSTR];
    __shared__ __align__(16) __nv_bfloat16 sBl[BK * BSTR];

    int tid = threadIdx.x;
    int warp = tid >> 5, lane = tid & 31;
    int wm = warp >> 1, wn = warp & 1;
    int m0 = blockIdx.y * BM, n0 = blockIdx.x * BN;

    float acc[2][4][4];
#pragma unroll
    for (int i = 0; i < 2; i++)
#pragma unroll
        for (int j = 0; j < 4; j++)
#pragma unroll
            for (int k = 0; k < 4; k++) acc[i][j][k] = 0.f;

    float4 aReg[4];
    uint4 bRegH, bRegL;

    // A loader indexing: 1024 float4 per tile, 4 per thread
    int arow[4], acol4[4];
#pragma unroll
    for (int r = 0; r < 4; r++) {
        int idx = r * 256 + tid;
        arow[r] = idx >> 3;
        acol4[r] = (idx & 7) << 2;
    }
    // B loader: 256 threads x 8 bf16 (16B) from hi and lo
    int brow = tid >> 3;
    int bn8 = (tid & 7) << 3;

    int iters = K / BK;

    // prefetch first tile into regs
    {
        int kk = 0;
#pragma unroll
        for (int r = 0; r < 4; r++) {
            int gm = m0 + arow[r];
            aReg[r] = (gm < M)
                ? *reinterpret_cast<const float4*>(A + (size_t)gm * K + kk + acol4[r])
                : make_float4(0.f, 0.f, 0.f, 0.f);
        }
        const __nv_bfloat16* ph = Bhi + (size_t)(kk + brow) * N + n0 + bn8;
        const __nv_bfloat16* pl = Blo + (size_t)(kk + brow) * N + n0 + bn8;
        bRegH = *reinterpret_cast<const uint4*>(ph);
        bRegL = *reinterpret_cast<const uint4*>(pl);
    }

    for (int it = 0; it < iters; ++it) {
        // stage regs -> smem (convert A to hi/lo)
#pragma unroll
        for (int r = 0; r < 4; r++) {
            float4 v = aReg[r];
            __nv_bfloat162 h01 = __floats2bfloat162_rn(v.x, v.y);
            __nv_bfloat162 h23 = __floats2bfloat162_rn(v.z, v.w);
            float rx = v.x - __bfloat162float(__low2bfloat16(h01));
            float ry = v.y - __bfloat162float(__high2bfloat16(h01));
            float rz = v.z - __bfloat162float(__low2bfloat16(h23));
            float rw = v.w - __bfloat162float(__high2bfloat16(h23));
            __nv_bfloat162 l01 = __floats2bfloat162_rn(rx, ry);
            __nv_bfloat162 l23 = __floats2bfloat162_rn(rz, rw);
            uint2 uh, ul;
            uh.x = *reinterpret_cast<uint32_t*>(&h01);
            uh.y = *reinterpret_cast<uint32_t*>(&h23);
            ul.x = *reinterpret_cast<uint32_t*>(&l01);
            ul.y = *reinterpret_cast<uint32_t*>(&l23);
            int off = arow[r] * ASTR + acol4[r];
            *reinterpret_cast<uint2*>(&sAh[off]) = uh;
            *reinterpret_cast<uint2*>(&sAl[off]) = ul;
        }
        {
            int off = brow * BSTR + bn8;
            *reinterpret_cast<uint4*>(&sBh[off]) = bRegH;
            *reinterpret_cast<uint4*>(&sBl[off]) = bRegL;
        }
        __syncthreads();

        // prefetch next tile
        if (it + 1 < iters) {
            int kk = (it + 1) * BK;
#pragma unroll
            for (int r = 0; r < 4; r++) {
                int gm = m0 + arow[r];
                aReg[r] = (gm < M)
                    ? *reinterpret_cast<const float4*>(A + (size_t)gm * K + kk + acol4[r])
                    : make_float4(0.f, 0.f, 0.f, 0.f);
            }
            const __nv_bfloat16* ph = Bhi + (size_t)(kk + brow) * N + n0 + bn8;
            const __nv_bfloat16* pl = Blo + (size_t)(kk + brow) * N + n0 + bn8;
            bRegH = *reinterpret_cast<const uint4*>(ph);
            bRegL = *reinterpret_cast<const uint4*>(pl);
        }

        // compute: 2 k16 steps
#pragma unroll
        for (int ks = 0; ks < 2; ks++) {
            uint32_t ah[2][4], al[2][4];
#pragma unroll
            for (int mt = 0; mt < 2; mt++) {
                int row = wm * 32 + mt * 16 + (lane & 15);
                int ko = ks * 16 + (lane >> 4) * 8;
                ldsm4(ah[mt], smem_u32(&sAh[row * ASTR + ko]));
                ldsm4(al[mt], smem_u32(&sAl[row * ASTR + ko]));
            }
            uint32_t bh[2][4], bl[2][4];
#pragma unroll
            for (int bt = 0; bt < 2; bt++) {
                int krow = ks * 16 + (lane & 15);
                int ncol = wn * 32 + bt * 16 + (lane >> 4) * 8;
                ldsm4t(bh[bt], smem_u32(&sBh[krow * BSTR + ncol]));
                ldsm4t(bl[bt], smem_u32(&sBl[krow * BSTR + ncol]));
            }
#pragma unroll
            for (int mt = 0; mt < 2; mt++)
#pragma unroll
                for (int nt = 0; nt < 4; nt++) {
                    const uint32_t* bph = &bh[nt >> 1][(nt & 1) * 2];
                    const uint32_t* bpl = &bl[nt >> 1][(nt & 1) * 2];
                    mma16816(acc[mt][nt], ah[mt], bph);  // hi*hi
                    mma16816(acc[mt][nt], al[mt], bph);  // lo*hi
                    mma16816(acc[mt][nt], ah[mt], bpl);  // hi*lo
                }
        }
        __syncthreads();
    }

    // epilogue
    int gid = lane >> 2, tig = lane & 3;
#pragma unroll
    for (int mt = 0; mt < 2; mt++) {
#pragma unroll
        for (int nt = 0; nt < 4; nt++) {
            int col = n0 + wn * 32 + nt * 8 + tig * 2;
            float bx = 0.f, by = 0.f;
            if (bias) { bx = bias[col]; by = bias[col + 1]; }
            int row0 = m0 + wm * 32 + mt * 16 + gid;
            float2 v0, v1;
            v0.x = acc[mt][nt][0] + bx; v0.y = acc[mt][nt][1] + by;
            v1.x = acc[mt][nt][2] + bx; v1.y = acc[mt][nt][3] + by;
            if (relu) {
                v0.x = fmaxf(v0.x, 0.f); v0.y = fmaxf(v0.y, 0.f);
                v1.x = fmaxf(v1.x, 0.f); v1.y = fmaxf(v1.y, 0.f);
            }
            if (row0 < M)
                *reinterpret_cast<float2*>(C + (size_t)row0 * N + col) = v0;
            if (row0 + 8 < M)
                *reinterpret_cast<float2*>(C + (size_t)(row0 + 8) * N + col) = v1;
        }
    }
}

// ---------------- GCN aggregation: warp per node ----------------------------
template <int F>
__global__ void k_gcn_agg(const float* __restrict__ t,
                          const float* __restrict__ bias,
                          float* __restrict__ out)
{
    int node = blockIdx.x * (blockDim.x >> 5) + (threadIdx.x >> 5);
    if (node >= Nn) return;
    int lane = threadIdx.x & 31;
    float acc[F / 32];
    float di = g_dinv[node];
    const float* selfrow = t + (size_t)node * F;
#pragma unroll
    for (int j = 0; j < F / 32; j++) acc[j] = di * selfrow[lane + 32 * j];
    int beg = g_rowptr[node], end = g_rowptr[node + 1];
    for (int p = beg; p < end; ++p) {
        int s = g_col[p];
        float c = g_dinv[s];
        const float* row = t + (size_t)s * F;
#pragma unroll
        for (int j = 0; j < F / 32; j++)
            acc[j] = fmaf(c, row[lane + 32 * j], acc[j]);
    }
#pragma unroll
    for (int j = 0; j < F / 32; j++) {
        float v = di * acc[j] + bias[lane + 32 * j];
        out[(size_t)node * F + lane + 32 * j] = fmaxf(v, 0.f);
    }
}

// ---------------- GAT: per-node attention scores ----------------------------
__global__ void k_gat_scores(const float* __restrict__ hg,
                             const float* __restrict__ att_src,
                             const float* __restrict__ att_dst)
{
    int node = blockIdx.x * (blockDim.x >> 5) + (threadIdx.x >> 5);
    if (node >= Nn) return;
    int lane = threadIdx.x & 31;
    const float* base = hg + (size_t)node * (HEADSn * EMBn);
#pragma unroll
    for (int h = 0; h < HEADSn; ++h) {
        float vs = 0.f, vd = 0.f;
#pragma unroll
        for (int j = 0; j < 4; j++) {
            float xv = base[h * EMBn + lane + 32 * j];
            vs = fmaf(xv, att_src[h * EMBn + lane + 32 * j], vs);
            vd = fmaf(xv, att_dst[h * EMBn + lane + 32 * j], vd);
        }
#pragma unroll
        for (int o = 16; o > 0; o >>= 1) {
            vs += __shfl_down_sync(0xffffffffu, vs, o);
            vd += __shfl_down_sync(0xffffffffu, vd, o);
        }
        if (lane == 0) {
            g_as[node * HEADSn + h] = vs;
            g_ad[node * HEADSn + h] = vd;
        }
    }
}

// ---------------- GAT: online max/sum per (node, head) ----------------------
__global__ void k_gat_stats() {
    int t = blockIdx.x * blockDim.x + threadIdx.x;
    if (t >= Nn * HEADSn) return;
    int node = t >> 3;
    int h = t & 7;
    float ad = g_ad[t];
    float m = lrelu(g_as[t] + ad);
    float s = 1.0f;
    int beg = g_rowptr[node], end = g_rowptr[node + 1];
    for (int p = beg; p < end; ++p) {
        int src = g_col[p];
        float e = lrelu(g_as[src * HEADSn + h] + ad);
        if (e > m) { s = s * __expf(m - e) + 1.f; m = e; }
        else       { s += __expf(e - m); }
    }
    g_m[t] = m; g_s[t] = s;
}

// ---------------- GAT: weighted aggregation, warp per (node, head) ----------
__global__ void k_gat_agg(const float* __restrict__ hg,
                          const float* __restrict__ bg,
                          float* __restrict__ out)
{
    int node = blockIdx.x;
    int h = threadIdx.x >> 5;
    int lane = threadIdx.x & 31;
    int t = node * HEADSn + h;
    float m = g_m[t];
    float sinv = 1.0f / g_s[t];
    float ad = g_ad[t];
    float acc[4];
    float aself = __expf(lrelu(g_as[t] + ad) - m) * sinv;
    const float* srow = hg + (size_t)node * (HEADSn * EMBn) + h * EMBn;
#pragma unroll
    for (int j = 0; j < 4; j++) acc[j] = aself * srow[lane + 32 * j];
    int beg = g_rowptr[node], end = g_rowptr[node + 1];
    for (int p = beg; p < end; ++p) {
        int src = g_col[p];
        float alpha = __expf(lrelu(g_as[src * HEADSn + h] + ad) - m) * sinv;
        const float* row = hg + (size_t)src * (HEADSn * EMBn) + h * EMBn;
#pragma unroll
        for (int j = 0; j < 4; j++)
            acc[j] = fmaf(alpha, row[lane + 32 * j], acc[j]);
    }
#pragma unroll
    for (int j = 0; j < 4; j++)
        out[(size_t)node * (HEADSn * EMBn) + h * EMBn + lane + 32 * j] =
            acc[j] + bg[h * EMBn + lane + 32 * j];
}

// ---------------- head: logits -> sigmoid ------------------------------------
__global__ void k_logits(const float* __restrict__ z,
                         const float* __restrict__ Wh2,
                         const float* __restrict__ bh2)
{
    int node = blockIdx.x * (blockDim.x >> 5) + (threadIdx.x >> 5);
    if (node >= Nn) return;
    int lane = threadIdx.x & 31;
    float v = 0.f;
    const float* row = z + (size_t)node * HIDn;
#pragma unroll
    for (int j = 0; j < HIDn / 32; j++)
        v = fmaf(row[lane + 32 * j], Wh2[lane + 32 * j], v);
#pragma unroll
    for (int o = 16; o > 0; o >>= 1) v += __shfl_down_sync(0xffffffffu, v, o);
    if (lane == 0) {
        float logit = v + bh2[0];
        g_w[node] = 1.0f / (1.0f + __expf(-logit));
    }
}

// ---------------- softmax over all N (deterministic two-level) --------------
__global__ void k_exp_partial() {
    __shared__ float red[256];
    int i = blockIdx.x * 256 + threadIdx.x;
    float e = 0.f;
    if (i < Nn) { e = __expf(g_w[i]); g_w[i] = e; }
    red[threadIdx.x] = e;
    __syncthreads();
    for (int o = 128; o > 0; o >>= 1) {
        if (threadIdx.x < o) red[threadIdx.x] += red[threadIdx.x + o];
        __syncthreads();
    }
    if (threadIdx.x == 0) g_partial[blockIdx.x] = red[0];
}

__global__ void k_sum_partials(int nb) {
    __shared__ float red[128];
    float v = ((int)threadIdx.x < nb) ? g_partial[threadIdx.x] : 0.f;
    red[threadIdx.x] = v;
    __syncthreads();
    for (int o = 64; o > 0; o >>= 1) {
        if (threadIdx.x < o) red[threadIdx.x] += red[threadIdx.x + o];
        __syncthreads();
    }
    if (threadIdx.x == 0) g_total = red[0];
}

__global__ void k_normalize(float* __restrict__ out) {
    int i = blockIdx.x * blockDim.x + threadIdx.x;
    if (i < Nn) out[i] = g_w[i] / g_total;
}

// ---------------- launch ------------------------------------------------------
extern "C" void kernel_launch(void* const* d_in, const int* in_sizes, int n_in,
                              void* d_out, int out_size)
{
    const float* x        = (const float*)d_in[0];
    const void*  ei       = d_in[1];
    const float* W1       = (const float*)d_in[2];
    const float* b1       = (const float*)d_in[3];
    const float* W2       = (const float*)d_in[4];
    const float* b2       = (const float*)d_in[5];
    const float* W3       = (const float*)d_in[6];
    const float* b3       = (const float*)d_in[7];
    const float* Wg       = (const float*)d_in[8];
    const float* att_src  = (const float*)d_in[9];
    const float* att_dst  = (const float*)d_in[10];
    const float* bg       = (const float*)d_in[11];
    const float* Wh1      = (const float*)d_in[12];
    const float* bh1      = (const float*)d_in[13];
    const float* Wh2      = (const float*)d_in[14];
    const float* bh2      = (const float*)d_in[15];
    float* out = (float*)d_out;

    float *bufA, *bufB;
    __nv_bfloat16 *whi, *wlo;
    cudaGetSymbolAddress((void**)&bufA, g_bufA);
    cudaGetSymbolAddress((void**)&bufB, g_bufB);
    cudaGetSymbolAddress((void**)&whi, g_whi);
    cudaGetSymbolAddress((void**)&wlo, g_wlo);

    // Graph/CSR prep
    k_detect<<<1, 32>>>((const int*)ei);
    k_zero_counts<<<(Nn + 255) / 256, 256>>>();
    k_count<<<(NE + 255) / 256, 256>>>(ei);
    k_dinv<<<(Nn + 255) / 256, 256>>>();
    k_scan<<<1, 1024>>>();
    k_fill<<<(NE + 255) / 256, 256>>>(ei);

    // Weight splits (hi/lo bf16)
    k_split<<<(65536 + 255) / 256, 256>>>(W1, whi + WOFF_W1, wlo + WOFF_W1, 65536);
    k_split<<<(65536 + 255) / 256, 256>>>(W2, whi + WOFF_W2, wlo + WOFF_W2, 65536);
    k_split<<<(32768 + 255) / 256, 256>>>(W3, whi + WOFF_W3, wlo + WOFF_W3, 32768);
    k_split<<<(131072 + 255) / 256, 256>>>(Wg, whi + WOFF_WG, wlo + WOFF_WG, 131072);
    k_split<<<(262144 + 255) / 256, 256>>>(Wh1, whi + WOFF_WH1, wlo + WOFF_WH1, 262144);

    dim3 blk(256);
    int mtiles = (Nn + BM - 1) / BM;
    // GCN 1: [N,256]@[256,256]
    { dim3 g(HIDn / BN, mtiles);
      k_gemm<<<g, blk>>>(x, whi + WOFF_W1, wlo + WOFF_W1, nullptr, bufA, Nn, HIDn, F_INn, 0); }
    k_gcn_agg<HIDn><<<(Nn + 7) / 8, 256>>>(bufA, b1, bufB);
    // GCN 2
    { dim3 g(HIDn / BN, mtiles);
      k_gemm<<<g, blk>>>(bufB, whi + WOFF_W2, wlo + WOFF_W2, nullptr, bufA, Nn, HIDn, HIDn, 0); }
    k_gcn_agg<HIDn><<<(Nn + 7) / 8, 256>>>(bufA, b2, bufB);
    // GCN 3 (256 -> 128)
    { dim3 g(EMBn / BN, mtiles);
      k_gemm<<<g, blk>>>(bufB, whi + WOFF_W3, wlo + WOFF_W3, nullptr, bufA, Nn, EMBn, HIDn, 0); }
    k_gcn_agg<EMBn><<<(Nn + 7) / 8, 256>>>(bufA, b3, bufB);
    // GAT projection (128 -> 1024)
    { dim3 g((HEADSn * EMBn) / BN, mtiles);
      k_gemm<<<g, blk>>>(bufB, whi + WOFF_WG, wlo + WOFF_WG, nullptr, bufA, Nn, HEADSn * EMBn, EMBn, 0); }
    k_gat_scores<<<(Nn + 7) / 8, 256>>>(bufA, att_src, att_dst);
    k_gat_stats<<<(Nn * HEADSn + 255) / 256, 256>>>();
    k_gat_agg<<<Nn, 256>>>(bufA, bg, bufB);
    // Head MLP (1024 -> 256) + relu
    { dim3 g(HIDn / BN, mtiles);
      k_gemm<<<g, blk>>>(bufB, whi + WOFF_WH1, wlo + WOFF_WH1, bh1, bufA, Nn, HIDn, HEADSn * EMBn, 1); }
    k_logits<<<(Nn + 7) / 8, 256>>>(bufA, Wh2, bh2);
    int nb = (Nn + 255) / 256;
    k_exp_partial<<<nb, 256>>>();
    k_sum_partials<<<1, 128>>>(nb);
    k_normalize<<<nb, 256>>>(out);
}